// round 2
// baseline (speedup 1.0000x reference)
#include <cuda_runtime.h>
#include <cuda_bf16.h>

// SegmentalEmotion: per-sample sliding-window segment means (two-phase).
// H: [B, T, D] fp32, lengths_sec: [B] fp32.
// Output: S_pad [B, maxS, D] fp32 + mask [B, maxS] fp32 appended (auto-detect).
//
// Plan replicated on-device in fp64 (bitwise-matches numpy):
//   dur = max(len, 0.001); fps = T/dur
//   win = max(1, rint(fps)); hop = max(1, rint(fps*0.5))
//   n = (T >= win) ? (T-win)/hop + 1 : 0 ; n==0 -> fallback full-T mean
//
// Key identity: win - 2*hop in {-1, 0, +1}, and window s = [s*hop, s*hop+win)
// equals hop-chunk sums P[s] + P[s+1] plus/minus at most one edge frame.
// Phase 1 reads H exactly once; phase 2 is tiny.

#define T_FRAMES 1500
#define D_DIM    768
#define D_VEC    (D_DIM / 4)   // 192 float4 lanes
#define NTHREADS 192
#define MAX_B    32
#define MAX_NHOP 64            // ceil(1500/25) = 60, padded

// hop-chunk partial sums: P[b, j, :]
__device__ float g_P[(size_t)MAX_B * MAX_NHOP * D_DIM];

struct Plan {
    long long win, hop, n_eff, nhop;
    bool fallback;
};

__device__ __forceinline__ Plan make_plan(float len) {
    Plan p;
    double dur = fmax((double)len, 0.001);
    double fps = (double)T_FRAMES / dur;
    p.win = llrint(fps);        if (p.win < 1) p.win = 1;   // WIN_SEC = 1.0
    p.hop = llrint(fps * 0.5);  if (p.hop < 1) p.hop = 1;   // HOP_SEC = 0.5
    long long n = ((long long)T_FRAMES >= p.win)
                      ? ((long long)T_FRAMES - p.win) / p.hop + 1 : 0;
    p.fallback = (n == 0);
    p.n_eff = p.fallback ? 1 : n;
    p.nhop = (T_FRAMES + p.hop - 1) / p.hop;
    return p;
}

// ---------- Phase 1: hop-chunk sums, reads H exactly once ----------
__global__ __launch_bounds__(NTHREADS)
void hop_sum_kernel(const float* __restrict__ H,
                    const float* __restrict__ lens)
{
    const int j   = blockIdx.x;
    const int b   = blockIdx.y;
    const int tid = threadIdx.x;

    Plan p = make_plan(lens[b]);
    if ((long long)j >= p.nhop) return;

    long long t0 = (long long)j * p.hop;
    long long t1 = t0 + p.hop;
    if (t1 > T_FRAMES) t1 = T_FRAMES;

    const float4* __restrict__ Hb =
        (const float4*)H + (size_t)b * T_FRAMES * D_VEC + tid;

    float4 acc = make_float4(0.f, 0.f, 0.f, 0.f);
    long long t = t0;
    for (; t + 8 <= t1; t += 8) {
        float4 v0 = Hb[(t + 0) * D_VEC];
        float4 v1 = Hb[(t + 1) * D_VEC];
        float4 v2 = Hb[(t + 2) * D_VEC];
        float4 v3 = Hb[(t + 3) * D_VEC];
        float4 v4 = Hb[(t + 4) * D_VEC];
        float4 v5 = Hb[(t + 5) * D_VEC];
        float4 v6 = Hb[(t + 6) * D_VEC];
        float4 v7 = Hb[(t + 7) * D_VEC];
        acc.x += v0.x + v1.x + v2.x + v3.x + v4.x + v5.x + v6.x + v7.x;
        acc.y += v0.y + v1.y + v2.y + v3.y + v4.y + v5.y + v6.y + v7.y;
        acc.z += v0.z + v1.z + v2.z + v3.z + v4.z + v5.z + v6.z + v7.z;
        acc.w += v0.w + v1.w + v2.w + v3.w + v4.w + v5.w + v6.w + v7.w;
    }
    for (; t < t1; ++t) {
        float4 v = Hb[t * D_VEC];
        acc.x += v.x; acc.y += v.y; acc.z += v.z; acc.w += v.w;
    }

    ((float4*)g_P)[((size_t)b * MAX_NHOP + j) * D_VEC + tid] = acc;
}

// ---------- Phase 2: combine chunk sums + edge correction, write out ----------
__global__ __launch_bounds__(NTHREADS)
void seg_out_kernel(const float* __restrict__ H,
                    const float* __restrict__ lens,
                    float* __restrict__ S,      // [B, maxS, D]
                    float* __restrict__ Mout,   // [B, maxS] or nullptr
                    int maxS)
{
    const int s   = blockIdx.x;
    const int b   = blockIdx.y;
    const int tid = threadIdx.x;

    Plan p = make_plan(lens[b]);
    const bool valid = ((long long)s < p.n_eff);

    float4* outRow = (float4*)(S + ((size_t)b * maxS + s) * D_DIM);

    if (!valid) {
        outRow[tid] = make_float4(0.f, 0.f, 0.f, 0.f);
        if (Mout != nullptr && tid == 0)
            Mout[(size_t)b * maxS + s] = 0.f;
        return;
    }

    const float4* __restrict__ Pb =
        (const float4*)g_P + (size_t)b * MAX_NHOP * D_VEC + tid;
    const float4* __restrict__ Hb =
        (const float4*)H + (size_t)b * T_FRAMES * D_VEC + tid;

    float4 acc = make_float4(0.f, 0.f, 0.f, 0.f);
    long long cnt;

    if (p.fallback) {
        // single mean over all T frames = sum of all chunk sums
        for (long long j = 0; j < p.nhop; ++j) {
            float4 v = Pb[j * D_VEC];
            acc.x += v.x; acc.y += v.y; acc.z += v.z; acc.w += v.w;
        }
        cnt = T_FRAMES;
    } else {
        long long start = (long long)s * p.hop;
        long long end   = start + p.win;          // <= T guaranteed for s < n
        // P[s] + P[s+1] covers [start, min(start+2*hop, T))
        float4 a = Pb[(size_t)s * D_VEC];
        float4 c = Pb[(size_t)(s + 1) * D_VEC];
        acc.x = a.x + c.x; acc.y = a.y + c.y;
        acc.z = a.z + c.z; acc.w = a.w + c.w;

        long long pcov = start + 2 * p.hop;
        if (pcov > T_FRAMES) pcov = T_FRAMES;

        // add missing frames [pcov, end)   (at most 1)
        for (long long t = pcov; t < end; ++t) {
            float4 v = Hb[t * D_VEC];
            acc.x += v.x; acc.y += v.y; acc.z += v.z; acc.w += v.w;
        }
        // subtract excess frames [end, pcov) (at most 1)
        for (long long t = end; t < pcov; ++t) {
            float4 v = Hb[t * D_VEC];
            acc.x -= v.x; acc.y -= v.y; acc.z -= v.z; acc.w -= v.w;
        }
        cnt = end - start;
        if (cnt < 1) cnt = 1;
    }

    const float inv = 1.0f / (float)cnt;
    outRow[tid] = make_float4(acc.x * inv, acc.y * inv, acc.z * inv, acc.w * inv);
    if (Mout != nullptr && tid == 0)
        Mout[(size_t)b * maxS + s] = 1.f;
}

extern "C" void kernel_launch(void* const* d_in, const int* in_sizes, int n_in,
                              void* d_out, int out_size)
{
    const float* H    = (const float*)d_in[0];
    const float* lens = (const float*)d_in[1];
    float* out        = (float*)d_out;

    const int B = in_sizes[1];  // 32

    // Infer maxS and mask presence from out_size (768, 769 coprime; maxS << 768).
    int maxS;
    bool has_mask;
    if (out_size % (B * (D_DIM + 1)) == 0) {
        maxS = out_size / (B * (D_DIM + 1));
        has_mask = true;
    } else {
        maxS = out_size / (B * D_DIM);
        has_mask = false;
    }

    float* Mout = has_mask ? (out + (size_t)B * maxS * D_DIM) : nullptr;

    dim3 grid1(60, B);   // max nhop = ceil(1500/25) = 60
    hop_sum_kernel<<<grid1, NTHREADS>>>(H, lens);

    dim3 grid2(maxS, B);
    seg_out_kernel<<<grid2, NTHREADS>>>(H, lens, out, Mout, maxS);
}

// round 3
// speedup vs baseline: 1.7267x; 1.7267x over previous
#include <cuda_runtime.h>
#include <cuda_bf16.h>

// SegmentalEmotion: per-sample sliding-window segment means (3-phase).
// H: [B, T, D] fp32, lengths_sec: [B] fp32.
// Output: S_pad [B, maxS, D] fp32 (+ mask [B, maxS] fp32 appended, auto-detect).
//
// Phase 0: plan kernel (1 warp) replicates numpy fp64 plan per sample, stores ints.
// Phase 1: uniform-size piece sums (each hop-chunk split into <=4 pieces of
//          ~19-38 frames) -> reads H exactly once with streaming loads.
// Phase 2: window sum = pieces of chunk s + chunk s+1 (+/- one edge frame),
//          scale by 1/win, write output + mask.

#define T_FRAMES 1500
#define D_DIM    768
#define D_VEC    (D_DIM / 4)   // 192 float4 lanes
#define NTHREADS 192
#define MAX_B    32
#define MAX_NHOP 60            // ceil(1500/25)
#define MAX_NP   4
#define PIECE_TGT 38           // target frames per phase-1 block

// plan[b]: {win, hop, n, nhop, np, plen, fallback, pad}
__device__ int g_plan[MAX_B][8];
// piece sums: P[b, j, p, :]
__device__ float g_P[(size_t)MAX_B * MAX_NHOP * MAX_NP * D_DIM];

// ---------- Phase 0: per-sample plan (fp64 paid once) ----------
__global__ void plan_kernel(const float* __restrict__ lens, int B)
{
    int b = threadIdx.x;
    if (b >= B) return;
    double dur = fmax((double)lens[b], 0.001);
    double fps = (double)T_FRAMES / dur;
    long long win = llrint(fps);        if (win < 1) win = 1;   // WIN_SEC = 1.0
    long long hop = llrint(fps * 0.5);  if (hop < 1) hop = 1;   // HOP_SEC = 0.5
    long long n = ((long long)T_FRAMES >= win)
                      ? ((long long)T_FRAMES - win) / hop + 1 : 0;
    int fallback = (n == 0);
    if (win > T_FRAMES + 1) win = T_FRAMES + 1;   // only used when !fallback
    if (hop > T_FRAMES) hop = T_FRAMES;
    int nhop = (int)((T_FRAMES + hop - 1) / hop);
    int np = (int)((hop + PIECE_TGT - 1) / PIECE_TGT);
    if (np > MAX_NP) np = MAX_NP;
    int plen = (int)((hop + np - 1) / np);
    g_plan[b][0] = (int)win;
    g_plan[b][1] = (int)hop;
    g_plan[b][2] = (int)(fallback ? 1 : n);   // n_eff
    g_plan[b][3] = nhop;
    g_plan[b][4] = np;
    g_plan[b][5] = plen;
    g_plan[b][6] = fallback;
    g_plan[b][7] = 0;
}

// ---------- Phase 1: uniform piece sums, reads H exactly once ----------
__global__ __launch_bounds__(NTHREADS)
void piece_sum_kernel(const float* __restrict__ H)
{
    const int j   = blockIdx.x;   // hop-chunk index
    const int p   = blockIdx.y;   // piece within chunk
    const int b   = blockIdx.z;
    const int tid = threadIdx.x;

    const int hop  = __ldg(&g_plan[b][1]);
    const int nhop = __ldg(&g_plan[b][3]);
    const int np   = __ldg(&g_plan[b][4]);
    const int plen = __ldg(&g_plan[b][5]);
    if (j >= nhop || p >= np) return;

    int t0 = j * hop + p * plen;
    int chunk_end = j * hop + hop;
    if (chunk_end > T_FRAMES) chunk_end = T_FRAMES;
    int t1 = t0 + plen;
    if (t1 > chunk_end) t1 = chunk_end;

    const float4* __restrict__ Hb =
        (const float4*)H + (size_t)b * T_FRAMES * D_VEC + tid;

    float4 acc = make_float4(0.f, 0.f, 0.f, 0.f);
    int t = t0;
    for (; t + 8 <= t1; t += 8) {
        float4 v0 = __ldcs(&Hb[(t + 0) * D_VEC]);
        float4 v1 = __ldcs(&Hb[(t + 1) * D_VEC]);
        float4 v2 = __ldcs(&Hb[(t + 2) * D_VEC]);
        float4 v3 = __ldcs(&Hb[(t + 3) * D_VEC]);
        float4 v4 = __ldcs(&Hb[(t + 4) * D_VEC]);
        float4 v5 = __ldcs(&Hb[(t + 5) * D_VEC]);
        float4 v6 = __ldcs(&Hb[(t + 6) * D_VEC]);
        float4 v7 = __ldcs(&Hb[(t + 7) * D_VEC]);
        acc.x += v0.x + v1.x + v2.x + v3.x + v4.x + v5.x + v6.x + v7.x;
        acc.y += v0.y + v1.y + v2.y + v3.y + v4.y + v5.y + v6.y + v7.y;
        acc.z += v0.z + v1.z + v2.z + v3.z + v4.z + v5.z + v6.z + v7.z;
        acc.w += v0.w + v1.w + v2.w + v3.w + v4.w + v5.w + v6.w + v7.w;
    }
    for (; t < t1; ++t) {
        float4 v = __ldcs(&Hb[t * D_VEC]);
        acc.x += v.x; acc.y += v.y; acc.z += v.z; acc.w += v.w;
    }

    ((float4*)g_P)[(((size_t)b * MAX_NHOP + j) * MAX_NP + p) * D_VEC + tid] = acc;
}

// ---------- Phase 2: combine piece sums + edge correction ----------
__global__ __launch_bounds__(NTHREADS)
void seg_out_kernel(const float* __restrict__ H,
                    float* __restrict__ S,      // [B, maxS, D]
                    float* __restrict__ Mout,   // [B, maxS] or nullptr
                    int maxS)
{
    const int s   = blockIdx.x;
    const int b   = blockIdx.y;
    const int tid = threadIdx.x;

    const int win      = __ldg(&g_plan[b][0]);
    const int hop      = __ldg(&g_plan[b][1]);
    const int n_eff    = __ldg(&g_plan[b][2]);
    const int nhop     = __ldg(&g_plan[b][3]);
    const int np       = __ldg(&g_plan[b][4]);
    const int fallback = __ldg(&g_plan[b][6]);

    float4* outRow = (float4*)(S + ((size_t)b * maxS + s) * D_DIM);

    if (s >= n_eff) {
        outRow[tid] = make_float4(0.f, 0.f, 0.f, 0.f);
        if (Mout != nullptr && tid == 0)
            Mout[(size_t)b * maxS + s] = 0.f;
        return;
    }

    const float4* __restrict__ Pb =
        (const float4*)g_P + (size_t)b * MAX_NHOP * MAX_NP * D_VEC + tid;
    const float4* __restrict__ Hb =
        (const float4*)H + (size_t)b * T_FRAMES * D_VEC + tid;

    float4 acc = make_float4(0.f, 0.f, 0.f, 0.f);
    int cnt;

    if (fallback) {
        for (int j = 0; j < nhop; ++j)
            for (int p = 0; p < np; ++p) {
                float4 v = Pb[((size_t)j * MAX_NP + p) * D_VEC];
                acc.x += v.x; acc.y += v.y; acc.z += v.z; acc.w += v.w;
            }
        cnt = T_FRAMES;
    } else {
        const int start = s * hop;
        const int end   = start + win;           // <= T by definition of n
        const bool have2 = (s + 1) < nhop;

        #pragma unroll
        for (int p = 0; p < MAX_NP; ++p) {
            if (p < np) {
                float4 v = Pb[((size_t)s * MAX_NP + p) * D_VEC];
                acc.x += v.x; acc.y += v.y; acc.z += v.z; acc.w += v.w;
            }
        }
        if (have2) {
            #pragma unroll
            for (int p = 0; p < MAX_NP; ++p) {
                if (p < np) {
                    float4 v = Pb[((size_t)(s + 1) * MAX_NP + p) * D_VEC];
                    acc.x += v.x; acc.y += v.y; acc.z += v.z; acc.w += v.w;
                }
            }
        }
        // chunks s (+ s+1) cover [start, cov_end)
        int cov_end = start + (have2 ? 2 : 1) * hop;
        if (cov_end > T_FRAMES) cov_end = T_FRAMES;

        for (int t = cov_end; t < end; ++t) {     // add missing (<=1 in practice)
            float4 v = Hb[t * D_VEC];
            acc.x += v.x; acc.y += v.y; acc.z += v.z; acc.w += v.w;
        }
        for (int t = end; t < cov_end; ++t) {     // subtract excess (<=1)
            float4 v = Hb[t * D_VEC];
            acc.x -= v.x; acc.y -= v.y; acc.z -= v.z; acc.w -= v.w;
        }
        cnt = win > 0 ? win : 1;
    }

    const float inv = 1.0f / (float)cnt;
    outRow[tid] = make_float4(acc.x * inv, acc.y * inv, acc.z * inv, acc.w * inv);
    if (Mout != nullptr && tid == 0)
        Mout[(size_t)b * maxS + s] = 1.f;
}

extern "C" void kernel_launch(void* const* d_in, const int* in_sizes, int n_in,
                              void* d_out, int out_size)
{
    const float* H    = (const float*)d_in[0];
    const float* lens = (const float*)d_in[1];
    float* out        = (float*)d_out;

    const int B = in_sizes[1];  // 32

    // Infer maxS and mask presence from out_size (768, 769 coprime; maxS << 768).
    int maxS;
    bool has_mask;
    if (out_size % (B * (D_DIM + 1)) == 0) {
        maxS = out_size / (B * (D_DIM + 1));
        has_mask = true;
    } else {
        maxS = out_size / (B * D_DIM);
        has_mask = false;
    }

    float* Mout = has_mask ? (out + (size_t)B * maxS * D_DIM) : nullptr;

    plan_kernel<<<1, 32>>>(lens, B);

    dim3 grid1(MAX_NHOP, MAX_NP, B);
    piece_sum_kernel<<<grid1, NTHREADS>>>(H);

    dim3 grid2(maxS, B);
    seg_out_kernel<<<grid2, NTHREADS>>>(H, out, Mout, maxS);
}